// round 14
// baseline (speedup 1.0000x reference)
#include <cuda_runtime.h>
#include <cstdint>

// ============================================================================
// out[f32,4096x4096] = mat1[i32] @ mat2[i32] + input[i32], values in [0,16)
// s8 IMMA path. R14: wave-quantization fix — BN 128->64, grid 1024->2048 CTAs
// (3.46 -> 6.92 waves over 296 slots). Mainloop per-warp schedule identical to
// R11 (proven 222us): 4 warps (2m x 2n) of 64x32, BK=128, 3 stages, 2 CTAs/SM.
// ============================================================================

#define MSZ 4096
#define BM 128
#define BN 64
#define BK 128
#define STAGES 3
#define NKT (MSZ / BK)             // 32
#define ROWB 144                   // padded SMEM row: 128 data + 16 pad
#define STAGE_A (BM * ROWB)        // 18432
#define STAGE_B (BN * ROWB)        // 9216
#define STAGE_BYTES (STAGE_A + STAGE_B)      // 27648
#define SMEM_DYN (STAGES * STAGE_BYTES)      // 82944 -> 2 CTAs/SM

__device__ __align__(128) uint8_t g_packA[(size_t)MSZ * MSZ];   // [M,K] s8
__device__ __align__(128) uint8_t g_packBt[(size_t)MSZ * MSZ];  // [N,K] s8 (B^T)

// ---------------------------------------------------------------- helpers
__device__ __forceinline__ uint32_t smem_u32(const void* p) {
    uint32_t a;
    asm("{ .reg .u64 t; cvta.to.shared.u64 t, %1; cvt.u32.u64 %0, t; }"
        : "=r"(a) : "l"(p));
    return a;
}

#define CPA16(dst, src) \
    asm volatile("cp.async.cg.shared.global [%0], [%1], 16;" :: "r"(dst), "l"(src) : "memory")
#define CPC() asm volatile("cp.async.commit_group;" ::: "memory")
#define CPW(n) asm volatile("cp.async.wait_group %0;" :: "n"(n) : "memory")

#define LDSM4(r0, r1, r2, r3, addr) \
    asm volatile("ldmatrix.sync.aligned.m8n8.x4.shared.b16 {%0,%1,%2,%3}, [%4];" \
                 : "=r"(r0), "=r"(r1), "=r"(r2), "=r"(r3) : "r"(addr))

#define MMA_S8(d, a, b0, b1) \
    asm volatile("mma.sync.aligned.m16n8k32.row.col.s32.s8.s8.s32 " \
                 "{%0,%1,%2,%3}, {%4,%5,%6,%7}, {%8,%9}, {%0,%1,%2,%3};" \
                 : "+r"((d)[0]), "+r"((d)[1]), "+r"((d)[2]), "+r"((d)[3]) \
                 : "r"((a)[0]), "r"((a)[1]), "r"((a)[2]), "r"((a)[3]), \
                   "r"(b0), "r"(b1))

// stage loader: 128 threads; A 1024 + B 512 16B chunks; 12 per thread.
#define LOAD_STAGE(kt, st) do {                                                           \
    const uint32_t sA_ = smbase + (st) * STAGE_BYTES;                                     \
    const uint32_t sB_ = sA_ + STAGE_A;                                                   \
    const uint8_t* pA_ = g_packA  + (size_t)m0 * MSZ + (size_t)(kt) * BK;                 \
    const uint8_t* pB_ = g_packBt + (size_t)n0 * MSZ + (size_t)(kt) * BK;                 \
    _Pragma("unroll")                                                                     \
    for (int i_ = 0; i_ < 8; i_++) {                                                      \
        const int row_ = ldRow + i_ * 16;                                                 \
        CPA16(sA_ + row_ * ROWB + ldSeg, pA_ + (size_t)row_ * MSZ + ldSeg);               \
    }                                                                                     \
    _Pragma("unroll")                                                                     \
    for (int i_ = 0; i_ < 4; i_++) {                                                      \
        const int row_ = ldRow + i_ * 16;                                                 \
        CPA16(sB_ + row_ * ROWB + ldSeg, pB_ + (size_t)row_ * MSZ + ldSeg);               \
    }                                                                                     \
    CPC();                                                                                \
} while (0)

// ---------------------------------------------------------------- fused pack
__global__ void pack_kernel(const int* __restrict__ A, const int* __restrict__ B) {
    if (blockIdx.x < 16384) {
        size_t i = (size_t)blockIdx.x * 256 + threadIdx.x;
        int4 v = ((const int4*)A)[i];
        uchar4 r;
        r.x = (uint8_t)v.x; r.y = (uint8_t)v.y; r.z = (uint8_t)v.z; r.w = (uint8_t)v.w;
        ((uchar4*)g_packA)[i] = r;
    } else {
        __shared__ uint8_t tsm[32][132];
        const int b2 = blockIdx.x - 16384;
        const int kb = (b2 & 31) * 128;
        const int nb = (b2 >> 5) * 32;
        const int t = threadIdx.x;
        const int kloc = t >> 5;
        const int nloc = t & 31;
        #pragma unroll
        for (int i = 0; i < 16; i++) {
            int k = kloc + i * 8;
            tsm[nloc][k] = (uint8_t)B[(size_t)(kb + k) * MSZ + nb + nloc];
        }
        __syncthreads();
        const int k4 = (t & 31) * 4;
        const int nrow = t >> 5;
        #pragma unroll
        for (int i = 0; i < 4; i++) {
            int n = nrow + i * 8;
            uchar4 v;
            v.x = tsm[n][k4]; v.y = tsm[n][k4 + 1]; v.z = tsm[n][k4 + 2]; v.w = tsm[n][k4 + 3];
            *(uchar4*)&g_packBt[(size_t)(nb + n) * MSZ + kb + k4] = v;
        }
    }
}

// ---------------------------------------------------------------- GEMM
// 128 threads, 4 warps 2(m) x 2(n); warp tile 64x32; CTA tile 128x64x128.
__global__ void __launch_bounds__(128, 2)
gemm_kernel(const int* __restrict__ gIn, float* __restrict__ gOut) {
    extern __shared__ uint8_t dsm[];
    const uint32_t smbase = smem_u32(dsm);

    const int tid = threadIdx.x;
    const int l = tid & 31;
    const int warp = tid >> 5;
    const int wm = warp >> 1;        // 0..1
    const int wn = warp & 1;         // 0..1
    const int m0 = blockIdx.y * BM;
    const int n0 = blockIdx.x * BN;

    const int ldRow = tid >> 3;          // 0..15
    const int ldSeg = (tid & 7) * 16;    // 0..112

    // ldmatrix lane-address components (m16n8k32 fragment layout)
    const int aRowL = (l & 7) + ((l >> 3) & 1) * 8;
    const int aChk  = ((l >> 4) & 1) * 16;
    const int bRowL = (l & 7) + ((l >> 4) & 1) * 8;
    const int bChk  = ((l >> 3) & 1) * 16;

    int acc[4][4][4];
    #pragma unroll
    for (int mi = 0; mi < 4; mi++)
        #pragma unroll
        for (int ni = 0; ni < 4; ni++)
            #pragma unroll
            for (int r = 0; r < 4; r++) acc[mi][ni][r] = 0;

    LOAD_STAGE(0, 0);
    LOAD_STAGE(1, 1);

    for (int kt = 0; kt < NKT; kt++) {
        CPW(STAGES - 2);
        __syncthreads();

        if (kt + STAGES - 1 < NKT) { LOAD_STAGE(kt + STAGES - 1, (kt + STAGES - 1) % STAGES); }
        else { CPC(); }

        const uint32_t sA = smbase + (kt % STAGES) * STAGE_BYTES;
        const uint32_t sB = sA + STAGE_A;

        #pragma unroll
        for (int ks = 0; ks < 4; ks++) {
            const uint32_t ko = (uint32_t)ks * 32;
            uint32_t a[4][4];
            #pragma unroll
            for (int mi = 0; mi < 4; mi++) {
                uint32_t addr = sA + (uint32_t)(wm * 64 + mi * 16 + aRowL) * ROWB
                              + aChk + ko;
                LDSM4(a[mi][0], a[mi][1], a[mi][2], a[mi][3], addr);
            }
            #pragma unroll
            for (int np = 0; np < 2; np++) {
                uint32_t r0, r1, r2, r3;
                uint32_t addr = sB + (uint32_t)(wn * 32 + np * 16 + bRowL) * ROWB
                              + bChk + ko;
                LDSM4(r0, r1, r2, r3, addr);
                #pragma unroll
                for (int mi = 0; mi < 4; mi++) {
                    MMA_S8(acc[mi][np * 2 + 0], a[mi], r0, r1);
                    MMA_S8(acc[mi][np * 2 + 1], a[mi], r2, r3);
                }
            }
        }
    }

    // Epilogue: int add (exact) then f32 convert; float2 stores.
    const int crow = l >> 2;
    const int ccol = (l & 3) * 2;
    #pragma unroll
    for (int mi = 0; mi < 4; mi++) {
        #pragma unroll
        for (int ni = 0; ni < 4; ni++) {
            const int row = m0 + wm * 64 + mi * 16 + crow;
            const int col = n0 + wn * 32 + ni * 8 + ccol;
            const size_t gi = (size_t)row * MSZ + col;
            const int2 in0 = *(const int2*)&gIn[gi];
            const int2 in1 = *(const int2*)&gIn[gi + (size_t)8 * MSZ];
            float2 o0, o1;
            o0.x = (float)(acc[mi][ni][0] + in0.x);
            o0.y = (float)(acc[mi][ni][1] + in0.y);
            o1.x = (float)(acc[mi][ni][2] + in1.x);
            o1.y = (float)(acc[mi][ni][3] + in1.y);
            *(float2*)&gOut[gi] = o0;
            *(float2*)&gOut[gi + (size_t)8 * MSZ] = o1;
        }
    }
}

// ---------------------------------------------------------------- launch
extern "C" void kernel_launch(void* const* d_in, const int* in_sizes, int n_in,
                              void* d_out, int out_size) {
    const int* inp  = (const int*)d_in[0];   // input_tensor [M,N]
    const int* mat1 = (const int*)d_in[1];   // [M,K]
    const int* mat2 = (const int*)d_in[2];   // [K,N]
    float* out = (float*)d_out;

    pack_kernel<<<16384 + 4096, 256>>>(mat1, mat2);

    static int smem_set = 0;
    if (!smem_set) {
        cudaFuncSetAttribute(gemm_kernel, cudaFuncAttributeMaxDynamicSharedMemorySize, SMEM_DYN);
        smem_set = 1;
    }
    gemm_kernel<<<dim3(MSZ / BN, MSZ / BM), 128, SMEM_DYN>>>(inp, out);
}

// round 15
// speedup vs baseline: 1.0416x; 1.0416x over previous
#include <cuda_runtime.h>
#include <cstdint>

// ============================================================================
// out[f32,4096x4096] = mat1[i32] @ mat2[i32] + input[i32], values in [0,16)
// s8 IMMA path. R15: test additive tensor+LDSM cost model — raise MMA/LDSM
// ratio to 4.0 (warp tile 64x64) while keeping occupancy 2:
// 128 thr, 4 warps (2m x 2n) of 64x64, BK=128, 3 stages, 2 CTAs/SM.
// ============================================================================

#define MSZ 4096
#define BM 128
#define BN 128
#define BK 128
#define STAGES 3
#define NKT (MSZ / BK)             // 32
#define ROWB 144                   // padded SMEM row: 128 data + 16 pad
#define STAGE_A (BM * ROWB)        // 18432
#define STAGE_B (BN * ROWB)        // 18432
#define STAGE_BYTES (STAGE_A + STAGE_B)      // 36864
#define SMEM_DYN (STAGES * STAGE_BYTES)      // 110592 -> 2 CTAs/SM

__device__ __align__(128) uint8_t g_packA[(size_t)MSZ * MSZ];   // [M,K] s8
__device__ __align__(128) uint8_t g_packBt[(size_t)MSZ * MSZ];  // [N,K] s8 (B^T)

// ---------------------------------------------------------------- helpers
__device__ __forceinline__ uint32_t smem_u32(const void* p) {
    uint32_t a;
    asm("{ .reg .u64 t; cvta.to.shared.u64 t, %1; cvt.u32.u64 %0, t; }"
        : "=r"(a) : "l"(p));
    return a;
}

#define CPA16(dst, src) \
    asm volatile("cp.async.cg.shared.global [%0], [%1], 16;" :: "r"(dst), "l"(src) : "memory")
#define CPC() asm volatile("cp.async.commit_group;" ::: "memory")
#define CPW(n) asm volatile("cp.async.wait_group %0;" :: "n"(n) : "memory")

#define LDSM4(r0, r1, r2, r3, addr) \
    asm volatile("ldmatrix.sync.aligned.m8n8.x4.shared.b16 {%0,%1,%2,%3}, [%4];" \
                 : "=r"(r0), "=r"(r1), "=r"(r2), "=r"(r3) : "r"(addr))

#define MMA_S8(d, a, b0, b1) \
    asm volatile("mma.sync.aligned.m16n8k32.row.col.s32.s8.s8.s32 " \
                 "{%0,%1,%2,%3}, {%4,%5,%6,%7}, {%8,%9}, {%0,%1,%2,%3};" \
                 : "+r"((d)[0]), "+r"((d)[1]), "+r"((d)[2]), "+r"((d)[3]) \
                 : "r"((a)[0]), "r"((a)[1]), "r"((a)[2]), "r"((a)[3]), \
                   "r"(b0), "r"(b1))

// stage loader: 128 threads; A 1024 + B 1024 16B chunks; 16 per thread.
#define LOAD_STAGE(kt, st) do {                                                           \
    const uint32_t sA_ = smbase + (st) * STAGE_BYTES;                                     \
    const uint32_t sB_ = sA_ + STAGE_A;                                                   \
    const uint8_t* pA_ = g_packA  + (size_t)m0 * MSZ + (size_t)(kt) * BK;                 \
    const uint8_t* pB_ = g_packBt + (size_t)n0 * MSZ + (size_t)(kt) * BK;                 \
    _Pragma("unroll")                                                                     \
    for (int i_ = 0; i_ < 8; i_++) {                                                      \
        const int row_ = ldRow + i_ * 16;                                                 \
        CPA16(sA_ + row_ * ROWB + ldSeg, pA_ + (size_t)row_ * MSZ + ldSeg);               \
        CPA16(sB_ + row_ * ROWB + ldSeg, pB_ + (size_t)row_ * MSZ + ldSeg);               \
    }                                                                                     \
    CPC();                                                                                \
} while (0)

// ---------------------------------------------------------------- fused pack
__global__ void pack_kernel(const int* __restrict__ A, const int* __restrict__ B) {
    if (blockIdx.x < 16384) {
        size_t i = (size_t)blockIdx.x * 256 + threadIdx.x;
        int4 v = ((const int4*)A)[i];
        uchar4 r;
        r.x = (uint8_t)v.x; r.y = (uint8_t)v.y; r.z = (uint8_t)v.z; r.w = (uint8_t)v.w;
        ((uchar4*)g_packA)[i] = r;
    } else {
        __shared__ uint8_t tsm[32][132];
        const int b2 = blockIdx.x - 16384;
        const int kb = (b2 & 31) * 128;
        const int nb = (b2 >> 5) * 32;
        const int t = threadIdx.x;
        const int kloc = t >> 5;
        const int nloc = t & 31;
        #pragma unroll
        for (int i = 0; i < 16; i++) {
            int k = kloc + i * 8;
            tsm[nloc][k] = (uint8_t)B[(size_t)(kb + k) * MSZ + nb + nloc];
        }
        __syncthreads();
        const int k4 = (t & 31) * 4;
        const int nrow = t >> 5;
        #pragma unroll
        for (int i = 0; i < 4; i++) {
            int n = nrow + i * 8;
            uchar4 v;
            v.x = tsm[n][k4]; v.y = tsm[n][k4 + 1]; v.z = tsm[n][k4 + 2]; v.w = tsm[n][k4 + 3];
            *(uchar4*)&g_packBt[(size_t)(nb + n) * MSZ + kb + k4] = v;
        }
    }
}

// ---------------------------------------------------------------- GEMM
// 128 threads, 4 warps 2(m) x 2(n); warp tile 64x64; CTA tile 128x128x128.
__global__ void __launch_bounds__(128, 2)
gemm_kernel(const int* __restrict__ gIn, float* __restrict__ gOut) {
    extern __shared__ uint8_t dsm[];
    const uint32_t smbase = smem_u32(dsm);

    const int tid = threadIdx.x;
    const int l = tid & 31;
    const int warp = tid >> 5;
    const int wm = warp >> 1;        // 0..1
    const int wn = warp & 1;         // 0..1
    const int m0 = blockIdx.y * BM;
    const int n0 = blockIdx.x * BN;

    const int ldRow = tid >> 3;          // 0..15
    const int ldSeg = (tid & 7) * 16;    // 0..112

    // ldmatrix lane-address components (m16n8k32 fragment layout)
    const int aRowL = (l & 7) + ((l >> 3) & 1) * 8;
    const int aChk  = ((l >> 4) & 1) * 16;
    const int bRowL = (l & 7) + ((l >> 4) & 1) * 8;
    const int bChk  = ((l >> 3) & 1) * 16;

    int acc[4][8][4];
    #pragma unroll
    for (int mi = 0; mi < 4; mi++)
        #pragma unroll
        for (int ni = 0; ni < 8; ni++)
            #pragma unroll
            for (int r = 0; r < 4; r++) acc[mi][ni][r] = 0;

    LOAD_STAGE(0, 0);
    LOAD_STAGE(1, 1);

    for (int kt = 0; kt < NKT; kt++) {
        CPW(STAGES - 2);
        __syncthreads();

        if (kt + STAGES - 1 < NKT) { LOAD_STAGE(kt + STAGES - 1, (kt + STAGES - 1) % STAGES); }
        else { CPC(); }

        const uint32_t sA = smbase + (kt % STAGES) * STAGE_BYTES;
        const uint32_t sB = sA + STAGE_A;

        #pragma unroll
        for (int ks = 0; ks < 4; ks++) {
            const uint32_t ko = (uint32_t)ks * 32;
            uint32_t a[4][4];
            #pragma unroll
            for (int mi = 0; mi < 4; mi++) {
                uint32_t addr = sA + (uint32_t)(wm * 64 + mi * 16 + aRowL) * ROWB
                              + aChk + ko;
                LDSM4(a[mi][0], a[mi][1], a[mi][2], a[mi][3], addr);
            }
            // 4 B ldmatrix.x4, each immediately feeding 8 MMAs
            #pragma unroll
            for (int np = 0; np < 4; np++) {
                uint32_t r0, r1, r2, r3;
                uint32_t addr = sB + (uint32_t)(wn * 64 + np * 16 + bRowL) * ROWB
                              + bChk + ko;
                LDSM4(r0, r1, r2, r3, addr);
                #pragma unroll
                for (int mi = 0; mi < 4; mi++) {
                    MMA_S8(acc[mi][np * 2 + 0], a[mi], r0, r1);
                    MMA_S8(acc[mi][np * 2 + 1], a[mi], r2, r3);
                }
            }
        }
    }

    // Epilogue: int add (exact) then f32 convert; float2 stores.
    const int crow = l >> 2;
    const int ccol = (l & 3) * 2;
    #pragma unroll
    for (int mi = 0; mi < 4; mi++) {
        #pragma unroll
        for (int ni = 0; ni < 8; ni++) {
            const int row = m0 + wm * 64 + mi * 16 + crow;
            const int col = n0 + wn * 64 + ni * 8 + ccol;
            const size_t gi = (size_t)row * MSZ + col;
            const int2 in0 = *(const int2*)&gIn[gi];
            const int2 in1 = *(const int2*)&gIn[gi + (size_t)8 * MSZ];
            float2 o0, o1;
            o0.x = (float)(acc[mi][ni][0] + in0.x);
            o0.y = (float)(acc[mi][ni][1] + in0.y);
            o1.x = (float)(acc[mi][ni][2] + in1.x);
            o1.y = (float)(acc[mi][ni][3] + in1.y);
            *(float2*)&gOut[gi] = o0;
            *(float2*)&gOut[gi + (size_t)8 * MSZ] = o1;
        }
    }
}

// ---------------------------------------------------------------- launch
extern "C" void kernel_launch(void* const* d_in, const int* in_sizes, int n_in,
                              void* d_out, int out_size) {
    const int* inp  = (const int*)d_in[0];   // input_tensor [M,N]
    const int* mat1 = (const int*)d_in[1];   // [M,K]
    const int* mat2 = (const int*)d_in[2];   // [K,N]
    float* out = (float*)d_out;

    pack_kernel<<<16384 + 4096, 256>>>(mat1, mat2);

    static int smem_set = 0;
    if (!smem_set) {
        cudaFuncSetAttribute(gemm_kernel, cudaFuncAttributeMaxDynamicSharedMemorySize, SMEM_DYN);
        smem_set = 1;
    }
    gemm_kernel<<<dim3(MSZ / BN, MSZ / BM), 128, SMEM_DYN>>>(inp, out);
}